// round 5
// baseline (speedup 1.0000x reference)
#include <cuda_runtime.h>
#include <cuda_fp16.h>
#include <math.h>
#include <stdint.h>

#define NPOS    80
#define HID     128
#define MAXB    8192

// ---- device scratch ----
__device__ __half g_W1h[NPOS * 256 * HID];          // 5.25 MB fp16 copy of W1
__device__ float  g_h0[(MAXB + 64) * HID];          // post-ELU h0 (+pad rows)
__device__ int    g_msg_is64;

__device__ __forceinline__ float elu1(float x) {
    return x > 0.0f ? x : expm1f(x);
}

// ---- f32x2 packed helpers ----
__device__ __forceinline__ unsigned long long pk2(float lo, float hi) {
    unsigned long long r;
    asm("mov.b64 %0, {%1, %2};" : "=l"(r) : "f"(lo), "f"(hi));
    return r;
}
__device__ __forceinline__ void upk2(unsigned long long v, float& lo, float& hi) {
    asm("mov.b64 {%0, %1}, %2;" : "=f"(lo), "=f"(hi) : "l"(v));
}
__device__ __forceinline__ void fma2(unsigned long long& d,
                                     unsigned long long a, unsigned long long b) {
    asm("fma.rn.f32x2 %0, %1, %2, %0;" : "+l"(d) : "l"(a), "l"(b));
}
__device__ __forceinline__ void add2(unsigned long long& d, unsigned long long a) {
    asm("add.rn.f32x2 %0, %0, %1;" : "+l"(d) : "l"(a));
}

// ============================================================================
// Phase 0: convert W1 -> fp16 (grid-wide) + int64 detection (warp 0 of block 0).
// Pure-BW kernel (~16 MB traffic).
// ============================================================================
#define CTHREADS 256
#define CBLOCKS  2560    // 2560*256 = 655360 float4 = full W1

__global__ __launch_bounds__(CTHREADS)
void convert_kernel(const float* __restrict__ W1, const int* __restrict__ msg)
{
    if (blockIdx.x == 0 && threadIdx.x < 32) {
        int t = threadIdx.x;
        int v = 0;
        #pragma unroll 4
        for (int i = t; i < 2048; i += 32) v |= __ldg(&msg[2 * i + 1]);
        unsigned ball = __ballot_sync(0xFFFFFFFFu, v != 0);
        if (t == 0) g_msg_is64 = (ball == 0u) ? 1 : 0;
    }
    int i = blockIdx.x * CTHREADS + threadIdx.x;
    float4 v = __ldg(&((const float4*)W1)[i]);
    __half2 h0 = __floats2half2_rn(v.x, v.y);
    __half2 h1 = __floats2half2_rn(v.z, v.w);
    uint2 o;
    o.x = *(unsigned*)&h0;
    o.y = *(unsigned*)&h1;
    ((uint2*)g_W1h)[i] = o;
}

// ============================================================================
// Phase 1: gather (fp16 table, fp32 accumulate).
// 16 rows/CTA, 128 threads: warp wr handles rows wr*4..wr*4+3; lane h4 owns
// hid cols 4*h4..4*h4+3. Per (row,p) a warp reads one contiguous 256B fp16 row.
// ============================================================================
#define GTILE 16
#define GTHREADS 128

__global__ __launch_bounds__(GTHREADS)
void gather_kernel(const int* __restrict__ msg,
                   const float* __restrict__ b1, int B)
{
    __shared__ unsigned char msg_sh[NPOS * GTILE];   // [p][r]

    const int t    = threadIdx.x;
    const int row0 = blockIdx.x * GTILE;
    const int is64 = g_msg_is64;

    for (int idx = t; idx < NPOS * GTILE; idx += GTHREADS) {
        int p = idx >> 4;
        int r = idx & 15;
        int row = row0 + r;
        int c = 0;
        if (row < B) {
            int gi = row * NPOS + p;
            c = is64 ? __ldg(&msg[2 * gi]) : __ldg(&msg[gi]);
        }
        msg_sh[idx] = (unsigned char)c;
    }
    __syncthreads();

    const int h4 = t & 31;
    const int wr = t >> 5;

    unsigned long long acc[4][2];
    {
        float4 bias1 = __ldg(&((const float4*)b1)[h4]);
        unsigned long long blo = pk2(bias1.x, bias1.y);
        unsigned long long bhi = pk2(bias1.z, bias1.w);
        #pragma unroll
        for (int i = 0; i < 4; i++) { acc[i][0] = blo; acc[i][1] = bhi; }
    }

    const uint2* W1v = (const uint2*)g_W1h + h4;    // lane's 8B within a 256B row
    #pragma unroll 2
    for (int p = 0; p < NPOS; p++) {
        unsigned c4 = *(const unsigned*)(msg_sh + p * GTILE + wr * 4);
        const uint2* Wp = W1v + (p << 13);          // + p*256*128/4 (uint2 units)
        #pragma unroll
        for (int i = 0; i < 4; i++) {
            int c = (c4 >> (8 * i)) & 255;
            uint2 u = __ldg(Wp + (c << 5));         // + c*128/4 ; 256B/warp coalesced
            float2 fa = __half22float2(*(const __half2*)&u.x);
            float2 fb = __half22float2(*(const __half2*)&u.y);
            add2(acc[i][0], *(unsigned long long*)&fa);
            add2(acc[i][1], *(unsigned long long*)&fb);
        }
    }

    #pragma unroll
    for (int i = 0; i < 4; i++) {
        int row = row0 + wr * 4 + i;
        if (row < B) {
            float4 v;
            upk2(acc[i][0], v.x, v.y);
            upk2(acc[i][1], v.z, v.w);
            v.x = elu1(v.x); v.y = elu1(v.y); v.z = elu1(v.z); v.w = elu1(v.w);
            ((float4*)g_h0)[row * 32 + h4] = v;
        }
    }
}

// ============================================================================
// Phase 2: 3 dense layers, f32x2 accumulators paired over k-parity.
// 28 rows/CTA, 224 threads, grid 293 ~= 2*148 (balanced 2 CTAs/SM).
// ============================================================================
#define MTILE 28
#define MTHREADS 224
#define MSMEM_FLOATS (16384 + MTILE * HID * 2)
#define MSMEM_BYTES  (MSMEM_FLOATS * 4)

__global__ __launch_bounds__(MTHREADS, 2)
void mlp_kernel(const float* __restrict__ W2, const float* __restrict__ b2,
                const float* __restrict__ W3, const float* __restrict__ b3,
                const float* __restrict__ W4, const float* __restrict__ b4,
                float* __restrict__ out, int B)
{
    extern __shared__ float smem[];
    float4* Wsh4 = (float4*)smem;
    float4* hA4  = (float4*)(smem + 16384);
    float4* hB4  = (float4*)(smem + 16384 + MTILE * HID);

    const int t    = threadIdx.x;
    const int row0 = blockIdx.x * MTILE;

    for (int idx = t; idx < MTILE * 32; idx += MTHREADS) {
        hA4[idx] = ((const float4*)g_h0)[row0 * 32 + idx];
    }

    const int j4 = t & 31;
    const int r0 = (t >> 5) * 4;

    const float* Wg[3] = {W2, W3, W4};
    const float* bg[3] = {b2, b3, b4};

    #pragma unroll 1
    for (int layer = 0; layer < 3; layer++) {
        const float4* hin  = (layer == 1) ? hB4 : hA4;
        float4*       hout = (layer == 1) ? hA4 : hB4;
        const bool    last = (layer == 2);

        const float4* Wg4 = (const float4*)Wg[layer];
        #pragma unroll 4
        for (int i = t; i < 4096; i += MTHREADS) Wsh4[i] = __ldg(&Wg4[i]);
        __syncthreads();

        unsigned long long a[4][4];
        {
            float4 bias = __ldg(&((const float4*)bg[layer])[j4]);
            #pragma unroll
            for (int r = 0; r < 4; r++) {
                a[r][0] = pk2(bias.x, 0.0f);
                a[r][1] = pk2(bias.y, 0.0f);
                a[r][2] = pk2(bias.z, 0.0f);
                a[r][3] = pk2(bias.w, 0.0f);
            }
        }

        #pragma unroll 4
        for (int k4 = 0; k4 < 32; k4++) {
            float4 w0 = Wsh4[(4 * k4 + 0) * 32 + j4];
            float4 w1 = Wsh4[(4 * k4 + 1) * 32 + j4];
            float4 w2 = Wsh4[(4 * k4 + 2) * 32 + j4];
            float4 w3 = Wsh4[(4 * k4 + 3) * 32 + j4];
            unsigned long long wp0[4], wp1[4];
            wp0[0] = pk2(w0.x, w1.x); wp0[1] = pk2(w0.y, w1.y);
            wp0[2] = pk2(w0.z, w1.z); wp0[3] = pk2(w0.w, w1.w);
            wp1[0] = pk2(w2.x, w3.x); wp1[1] = pk2(w2.y, w3.y);
            wp1[2] = pk2(w2.z, w3.z); wp1[3] = pk2(w2.w, w3.w);
            #pragma unroll
            for (int r = 0; r < 4; r++) {
                ulonglong2 hv = *(const ulonglong2*)&hin[(r0 + r) * 32 + k4];
                fma2(a[r][0], hv.x, wp0[0]);
                fma2(a[r][1], hv.x, wp0[1]);
                fma2(a[r][2], hv.x, wp0[2]);
                fma2(a[r][3], hv.x, wp0[3]);
                fma2(a[r][0], hv.y, wp1[0]);
                fma2(a[r][1], hv.y, wp1[1]);
                fma2(a[r][2], hv.y, wp1[2]);
                fma2(a[r][3], hv.y, wp1[3]);
            }
        }

        if (!last) {
            #pragma unroll
            for (int r = 0; r < 4; r++) {
                float4 v; float lo, hi;
                upk2(a[r][0], lo, hi); v.x = elu1(lo + hi);
                upk2(a[r][1], lo, hi); v.y = elu1(lo + hi);
                upk2(a[r][2], lo, hi); v.z = elu1(lo + hi);
                upk2(a[r][3], lo, hi); v.w = elu1(lo + hi);
                hout[(r0 + r) * 32 + j4] = v;
            }
            __syncthreads();
        } else {
            #pragma unroll
            for (int r = 0; r < 4; r++) {
                int row = row0 + r0 + r;
                if (row < B) {
                    float4 v; float lo, hi;
                    upk2(a[r][0], lo, hi); v.x = elu1(lo + hi);
                    upk2(a[r][1], lo, hi); v.y = elu1(lo + hi);
                    upk2(a[r][2], lo, hi); v.z = elu1(lo + hi);
                    upk2(a[r][3], lo, hi); v.w = elu1(lo + hi);
                    ((float4*)out)[row * 32 + j4] = v;
                }
            }
        }
    }
}

extern "C" void kernel_launch(void* const* d_in, const int* in_sizes, int n_in,
                              void* d_out, int out_size)
{
    const int*   msg = (const int*)  d_in[0];
    const float* W1  = (const float*)d_in[1];
    const float* b1  = (const float*)d_in[2];
    const float* W2  = (const float*)d_in[3];
    const float* b2  = (const float*)d_in[4];
    const float* W3  = (const float*)d_in[5];
    const float* b3  = (const float*)d_in[6];
    const float* W4  = (const float*)d_in[7];
    const float* b4  = (const float*)d_in[8];
    float* out = (float*)d_out;

    const int B = in_sizes[0] / NPOS;   // 8192

    cudaFuncSetAttribute(mlp_kernel,
                         cudaFuncAttributeMaxDynamicSharedMemorySize, MSMEM_BYTES);

    convert_kernel<<<CBLOCKS, CTHREADS>>>(W1, msg);

    int ggrid = (B + GTILE - 1) / GTILE;   // 512
    gather_kernel<<<ggrid, GTHREADS>>>(msg, b1, B);

    int mgrid = (B + MTILE - 1) / MTILE;   // 293
    mlp_kernel<<<mgrid, MTHREADS, MSMEM_BYTES>>>(W2, b2, W3, b3, W4, b4, out, B);
}

// round 6
// speedup vs baseline: 1.7362x; 1.7362x over previous
#include <cuda_runtime.h>
#include <cuda_fp16.h>
#include <math.h>
#include <stdint.h>

#define NPOS    80
#define HID     128
#define MAXB    8192

// ---- device scratch ----
__device__ __half g_W1h[NPOS * 256 * HID];    // 5.25 MB fp16 copy of W1
__device__ float  g_h0[(MAXB + 64) * HID];    // post-ELU h0
__device__ int    g_msg_is64;

__device__ __forceinline__ float elu1(float x) {
    return x > 0.0f ? x : expm1f(x);
}

// ---- f32x2 packed helpers ----
__device__ __forceinline__ unsigned long long pk2(float lo, float hi) {
    unsigned long long r;
    asm("mov.b64 %0, {%1, %2};" : "=l"(r) : "f"(lo), "f"(hi));
    return r;
}
__device__ __forceinline__ void upk2(unsigned long long v, float& lo, float& hi) {
    asm("mov.b64 {%0, %1}, %2;" : "=f"(lo), "=f"(hi) : "l"(v));
}
__device__ __forceinline__ void fma2(unsigned long long& d,
                                     unsigned long long a, unsigned long long b) {
    asm("fma.rn.f32x2 %0, %1, %2, %0;" : "+l"(d) : "l"(a), "l"(b));
}
__device__ __forceinline__ void add2(unsigned long long& d, unsigned long long a) {
    asm("add.rn.f32x2 %0, %0, %1;" : "+l"(d) : "l"(a));
}
// half2 (as uint) -> f32x2
__device__ __forceinline__ unsigned long long h2f2(unsigned u) {
    float2 f = __half22float2(*(const __half2*)&u);
    return *(unsigned long long*)&f;
}

// ============================================================================
// Phase 0: W1 -> fp16 (4 float4/thread for MLP) + int64 detect in block 0.
// ============================================================================
#define CTHREADS 256
#define CBLOCKS  640    // 640*256*4 = 655360 float4 = full W1

__global__ __launch_bounds__(CTHREADS)
void convert_kernel(const float* __restrict__ W1, const int* __restrict__ msg)
{
    if (blockIdx.x == 0 && threadIdx.x < 32) {
        int t = threadIdx.x;
        int v = 0;
        #pragma unroll 4
        for (int i = t; i < 2048; i += 32) v |= __ldg(&msg[2 * i + 1]);
        unsigned ball = __ballot_sync(0xFFFFFFFFu, v != 0);
        if (t == 0) g_msg_is64 = (ball == 0u) ? 1 : 0;
    }
    const int base = blockIdx.x * CTHREADS + threadIdx.x;
    const int step = CBLOCKS * CTHREADS;
    #pragma unroll
    for (int j = 0; j < 4; j++) {
        int i = base + j * step;
        float4 v = __ldg(&((const float4*)W1)[i]);
        __half2 h0 = __floats2half2_rn(v.x, v.y);
        __half2 h1 = __floats2half2_rn(v.z, v.w);
        uint2 o;
        o.x = *(unsigned*)&h0;
        o.y = *(unsigned*)&h1;
        ((uint2*)g_W1h)[i] = o;
    }
}

// ============================================================================
// Phase 1: gather (fp16 table, f32x2 accumulate).
// 256 threads, 16 rows/CTA -> 8 warps x 2 rows. Within a warp, lanes 0-15
// serve row A and lanes 16-31 row B; each lane owns 8 hid cols (16B of the
// 256B fp16 row). One LDG.128 per (2 rows, position).
// ============================================================================
#define GTILE 16
#define GTHREADS 256

__global__ __launch_bounds__(GTHREADS)
void gather_kernel(const int* __restrict__ msg,
                   const float* __restrict__ b1, int B)
{
    __shared__ unsigned char msg_sh[GTILE * NPOS];   // [r][p], row stride 80

    const int t    = threadIdx.x;
    const int row0 = blockIdx.x * GTILE;
    const int is64 = g_msg_is64;

    for (int idx = t; idx < GTILE * NPOS; idx += GTHREADS) {
        int r = idx / NPOS;
        int p = idx - r * NPOS;
        int row = row0 + r;
        int c = 0;
        if (row < B) {
            int gi = row * NPOS + p;
            c = is64 ? __ldg(&msg[2 * gi]) : __ldg(&msg[gi]);
        }
        msg_sh[idx] = (unsigned char)c;
    }
    __syncthreads();

    const int lane = t & 31;
    const int w    = t >> 5;
    const int hsel = lane >> 4;            // 0 -> row A, 1 -> row B
    const int colg = lane & 15;            // 16B group: hid cols colg*8..+7
    const int rowL = w * 2 + hsel;

    unsigned long long acc[4];
    {
        float4 b0 = __ldg(&((const float4*)b1)[colg * 2]);
        float4 b1v = __ldg(&((const float4*)b1)[colg * 2 + 1]);
        acc[0] = pk2(b0.x, b0.y);
        acc[1] = pk2(b0.z, b0.w);
        acc[2] = pk2(b1v.x, b1v.y);
        acc[3] = pk2(b1v.z, b1v.w);
    }

    const uint4* Wb = (const uint4*)g_W1h + colg;        // row = 16 uint4
    const unsigned* mrow = (const unsigned*)(msg_sh + rowL * NPOS);

    #pragma unroll 4
    for (int p4 = 0; p4 < NPOS / 4; p4++) {
        unsigned c4 = mrow[p4];
        #pragma unroll
        for (int i = 0; i < 4; i++) {
            int c = (c4 >> (8 * i)) & 255;
            int p = p4 * 4 + i;
            uint4 u = __ldg(Wb + (((p << 8) + c) << 4));  // (p*256+c)*16
            add2(acc[0], h2f2(u.x));
            add2(acc[1], h2f2(u.y));
            add2(acc[2], h2f2(u.z));
            add2(acc[3], h2f2(u.w));
        }
    }

    int row = row0 + rowL;
    if (row < B) {
        float4 v0, v1; float lo, hi;
        upk2(acc[0], lo, hi); v0.x = elu1(lo); v0.y = elu1(hi);
        upk2(acc[1], lo, hi); v0.z = elu1(lo); v0.w = elu1(hi);
        upk2(acc[2], lo, hi); v1.x = elu1(lo); v1.y = elu1(hi);
        upk2(acc[3], lo, hi); v1.z = elu1(lo); v1.w = elu1(hi);
        ((float4*)g_h0)[row * 32 + colg * 2]     = v0;
        ((float4*)g_h0)[row * 32 + colg * 2 + 1] = v1;
    }
}

// ============================================================================
// Phase 2: 3 dense layers, f32x2 over k-parity, weights pre-paired in smem.
// planeA[k2][j4] = {W[2k2][4j4], W[2k2+1][4j4], W[2k2][4j4+1], W[2k2+1][4j4+1]}
// planeB[k2][j4] = same for cols 4j4+2, 4j4+3.
// ============================================================================
#define MTILE 28
#define MTHREADS 224
#define MSMEM_FLOATS (16384 + MTILE * HID * 2)   // 64KB planes + hA + hB
#define MSMEM_BYTES  (MSMEM_FLOATS * 4)

__global__ __launch_bounds__(MTHREADS, 2)
void mlp_kernel(const float* __restrict__ W2, const float* __restrict__ b2,
                const float* __restrict__ W3, const float* __restrict__ b3,
                const float* __restrict__ W4, const float* __restrict__ b4,
                float* __restrict__ out, int B)
{
    extern __shared__ float smem[];
    float4*     plane4 = (float4*)smem;              // [0,2048): A, [2048,4096): B
    ulonglong2* planeU = (ulonglong2*)smem;
    float4*     hA4    = (float4*)(smem + 16384);
    float4*     hB4    = (float4*)(smem + 16384 + MTILE * HID);

    const int t    = threadIdx.x;
    const int row0 = blockIdx.x * MTILE;

    for (int idx = t; idx < MTILE * 32; idx += MTHREADS) {
        hA4[idx] = ((const float4*)g_h0)[row0 * 32 + idx];
    }

    const int j4 = t & 31;
    const int r0 = (t >> 5) * 4;

    const float* Wg[3] = {W2, W3, W4};
    const float* bg[3] = {b2, b3, b4};

    #pragma unroll 1
    for (int layer = 0; layer < 3; layer++) {
        const float4* hin  = (layer == 1) ? hB4 : hA4;
        float4*       hout = (layer == 1) ? hA4 : hB4;
        const bool    last = (layer == 2);

        // Stage weights, pairing k-adjacent rows.
        const float4* Wg4 = (const float4*)Wg[layer];
        for (int task = t; task < 2048; task += MTHREADS) {
            int k2 = task >> 5;
            int j  = task & 31;
            float4 a = __ldg(&Wg4[(2 * k2) * 32 + j]);
            float4 b = __ldg(&Wg4[(2 * k2 + 1) * 32 + j]);
            float4 pA; pA.x = a.x; pA.y = b.x; pA.z = a.y; pA.w = b.y;
            float4 pB; pB.x = a.z; pB.y = b.z; pB.z = a.w; pB.w = b.w;
            plane4[task]        = pA;
            plane4[2048 + task] = pB;
        }
        __syncthreads();

        unsigned long long a[4][4];
        {
            float4 bias = __ldg(&((const float4*)bg[layer])[j4]);
            #pragma unroll
            for (int r = 0; r < 4; r++) {
                a[r][0] = pk2(bias.x, 0.0f);
                a[r][1] = pk2(bias.y, 0.0f);
                a[r][2] = pk2(bias.z, 0.0f);
                a[r][3] = pk2(bias.w, 0.0f);
            }
        }

        #pragma unroll 4
        for (int k4 = 0; k4 < 32; k4++) {
            int k2 = 2 * k4;
            ulonglong2 wA0 = planeU[k2 * 32 + j4];              // cols 0,1 @ k2
            ulonglong2 wB0 = planeU[2048 + k2 * 32 + j4];       // cols 2,3 @ k2
            ulonglong2 wA1 = planeU[(k2 + 1) * 32 + j4];        // cols 0,1 @ k2+1
            ulonglong2 wB1 = planeU[2048 + (k2 + 1) * 32 + j4]; // cols 2,3 @ k2+1
            #pragma unroll
            for (int r = 0; r < 4; r++) {
                ulonglong2 hv = *(const ulonglong2*)&hin[(r0 + r) * 32 + k4];
                fma2(a[r][0], hv.x, wA0.x);
                fma2(a[r][1], hv.x, wA0.y);
                fma2(a[r][2], hv.x, wB0.x);
                fma2(a[r][3], hv.x, wB0.y);
                fma2(a[r][0], hv.y, wA1.x);
                fma2(a[r][1], hv.y, wA1.y);
                fma2(a[r][2], hv.y, wB1.x);
                fma2(a[r][3], hv.y, wB1.y);
            }
        }

        if (!last) {
            #pragma unroll
            for (int r = 0; r < 4; r++) {
                float4 v; float lo, hi;
                upk2(a[r][0], lo, hi); v.x = elu1(lo + hi);
                upk2(a[r][1], lo, hi); v.y = elu1(lo + hi);
                upk2(a[r][2], lo, hi); v.z = elu1(lo + hi);
                upk2(a[r][3], lo, hi); v.w = elu1(lo + hi);
                hout[(r0 + r) * 32 + j4] = v;
            }
            __syncthreads();
        } else {
            #pragma unroll
            for (int r = 0; r < 4; r++) {
                int row = row0 + r0 + r;
                if (row < B) {
                    float4 v; float lo, hi;
                    upk2(a[r][0], lo, hi); v.x = elu1(lo + hi);
                    upk2(a[r][1], lo, hi); v.y = elu1(lo + hi);
                    upk2(a[r][2], lo, hi); v.z = elu1(lo + hi);
                    upk2(a[r][3], lo, hi); v.w = elu1(lo + hi);
                    ((float4*)out)[row * 32 + j4] = v;
                }
            }
        }
    }
}

extern "C" void kernel_launch(void* const* d_in, const int* in_sizes, int n_in,
                              void* d_out, int out_size)
{
    const int*   msg = (const int*)  d_in[0];
    const float* W1  = (const float*)d_in[1];
    const float* b1  = (const float*)d_in[2];
    const float* W2  = (const float*)d_in[3];
    const float* b2  = (const float*)d_in[4];
    const float* W3  = (const float*)d_in[5];
    const float* b3  = (const float*)d_in[6];
    const float* W4  = (const float*)d_in[7];
    const float* b4  = (const float*)d_in[8];
    float* out = (float*)d_out;

    const int B = in_sizes[0] / NPOS;   // 8192

    cudaFuncSetAttribute(mlp_kernel,
                         cudaFuncAttributeMaxDynamicSharedMemorySize, MSMEM_BYTES);

    convert_kernel<<<CBLOCKS, CTHREADS>>>(W1, msg);

    int ggrid = (B + GTILE - 1) / GTILE;   // 512
    gather_kernel<<<ggrid, GTHREADS>>>(msg, b1, B);

    int mgrid = (B + MTILE - 1) / MTILE;   // 293
    mlp_kernel<<<mgrid, MTHREADS, MSMEM_BYTES>>>(W2, b2, W3, b3, W4, b4, out, B);
}

// round 7
// speedup vs baseline: 1.7620x; 1.0148x over previous
#include <cuda_runtime.h>
#include <cuda_fp16.h>
#include <math.h>
#include <stdint.h>

#define NPOS    80
#define HID     128
#define MAXB    8192

// ---- device scratch ----
__device__ __half g_W1h[NPOS * 256 * HID];    // 5.25 MB fp16 copy of W1
__device__ float  g_Wp[3 * 4096 * 4];         // pre-paired W2/W3/W4 (192 KB)
__device__ float  g_h0[(MAXB + 64) * HID];    // post-ELU h0
__device__ int    g_msg_is64;

__device__ __forceinline__ float elu1(float x) {
    return x > 0.0f ? x : expm1f(x);
}

// ---- f32x2 packed helpers ----
__device__ __forceinline__ unsigned long long pk2(float lo, float hi) {
    unsigned long long r;
    asm("mov.b64 %0, {%1, %2};" : "=l"(r) : "f"(lo), "f"(hi));
    return r;
}
__device__ __forceinline__ void upk2(unsigned long long v, float& lo, float& hi) {
    asm("mov.b64 {%0, %1}, %2;" : "=f"(lo), "=f"(hi) : "l"(v));
}
__device__ __forceinline__ void fma2(unsigned long long& d,
                                     unsigned long long a, unsigned long long b) {
    asm("fma.rn.f32x2 %0, %1, %2, %0;" : "+l"(d) : "l"(a), "l"(b));
}
__device__ __forceinline__ void add2(unsigned long long& d, unsigned long long a) {
    asm("add.rn.f32x2 %0, %0, %1;" : "+l"(d) : "l"(a));
}
__device__ __forceinline__ unsigned long long h2f2(unsigned u) {
    float2 f = __half22float2(*(const __half2*)&u);
    return *(unsigned long long*)&f;
}

// ============================================================================
// Phase 0: (a) W1 -> fp16, 8 float4/thread, loads batched in registers;
//          (b) pre-pair W2/3/4 into g_Wp; (c) int64 detect (block 0, warp 0).
// ============================================================================
#define CTHREADS 256
#define CW1BLOCKS 320                 // 320*256*8 = 655360 float4 = full W1
#define CPAIRBLOCKS 24                // 24*256 = 6144 pairing tasks
#define CBLOCKS (CW1BLOCKS + CPAIRBLOCKS)

__global__ __launch_bounds__(CTHREADS)
void convert_kernel(const float* __restrict__ W1,
                    const float* __restrict__ W2,
                    const float* __restrict__ W3,
                    const float* __restrict__ W4,
                    const int* __restrict__ msg)
{
    const int bx = blockIdx.x;
    const int t  = threadIdx.x;

    if (bx == 0 && t < 32) {
        int v = 0;
        #pragma unroll 4
        for (int i = t; i < 2048; i += 32) v |= __ldg(&msg[2 * i + 1]);
        unsigned ball = __ballot_sync(0xFFFFFFFFu, v != 0);
        if (t == 0) g_msg_is64 = (ball == 0u) ? 1 : 0;
    }

    if (bx < CW1BLOCKS) {
        // 8 independent float4 loads held in registers, then convert+store.
        const int base = bx * CTHREADS + t;
        const int step = CW1BLOCKS * CTHREADS;
        float4 v[8];
        #pragma unroll
        for (int j = 0; j < 8; j++) v[j] = __ldg(&((const float4*)W1)[base + j * step]);
        #pragma unroll
        for (int j = 0; j < 8; j++) {
            __half2 h0 = __floats2half2_rn(v[j].x, v[j].y);
            __half2 h1 = __floats2half2_rn(v[j].z, v[j].w);
            uint2 o;
            o.x = *(unsigned*)&h0;
            o.y = *(unsigned*)&h1;
            ((uint2*)g_W1h)[base + j * step] = o;
        }
    } else {
        // Pre-pair W2/3/4: per layer, planeA[i] pairs cols (4j,4j+1) of rows
        // (2k2, 2k2+1); planeB[i] pairs cols (4j+2, 4j+3).
        int task  = (bx - CW1BLOCKS) * CTHREADS + t;   // 0..6143
        int layer = task >> 11;                        // /2048
        int i     = task & 2047;
        int k2 = i >> 5;
        int j  = i & 31;
        const float* Wsrc = (layer == 0) ? W2 : (layer == 1) ? W3 : W4;
        float4 a = __ldg(&((const float4*)Wsrc)[(2 * k2) * 32 + j]);
        float4 b = __ldg(&((const float4*)Wsrc)[(2 * k2 + 1) * 32 + j]);
        float4 pA; pA.x = a.x; pA.y = b.x; pA.z = a.y; pA.w = b.y;
        float4 pB; pB.x = a.z; pB.y = b.z; pB.z = a.w; pB.w = b.w;
        ((float4*)g_Wp)[layer * 4096 + i]        = pA;
        ((float4*)g_Wp)[layer * 4096 + 2048 + i] = pB;
    }
}

// ============================================================================
// Phase 1: gather (fp16 table, f32x2 accumulate).
// 256 threads, 16 rows/CTA -> 8 warps x 2 rows; lanes 0-15 row A, 16-31 row B;
// lane owns 16B (8 hid cols) of the 256B fp16 row.
// ============================================================================
#define GTILE 16
#define GTHREADS 256

__global__ __launch_bounds__(GTHREADS)
void gather_kernel(const int* __restrict__ msg,
                   const float* __restrict__ b1, int B)
{
    __shared__ unsigned char msg_sh[GTILE * NPOS];   // [r][p]

    const int t    = threadIdx.x;
    const int row0 = blockIdx.x * GTILE;
    const int is64 = g_msg_is64;

    for (int idx = t; idx < GTILE * NPOS; idx += GTHREADS) {
        int r = idx / NPOS;
        int p = idx - r * NPOS;
        int row = row0 + r;
        int c = 0;
        if (row < B) {
            int gi = row * NPOS + p;
            c = is64 ? __ldg(&msg[2 * gi]) : __ldg(&msg[gi]);
        }
        msg_sh[idx] = (unsigned char)c;
    }
    __syncthreads();

    const int lane = t & 31;
    const int w    = t >> 5;
    const int hsel = lane >> 4;
    const int colg = lane & 15;
    const int rowL = w * 2 + hsel;

    unsigned long long acc[4];
    {
        float4 b0 = __ldg(&((const float4*)b1)[colg * 2]);
        float4 b1v = __ldg(&((const float4*)b1)[colg * 2 + 1]);
        acc[0] = pk2(b0.x, b0.y);
        acc[1] = pk2(b0.z, b0.w);
        acc[2] = pk2(b1v.x, b1v.y);
        acc[3] = pk2(b1v.z, b1v.w);
    }

    const uint4* Wb = (const uint4*)g_W1h + colg;
    const unsigned* mrow = (const unsigned*)(msg_sh + rowL * NPOS);

    #pragma unroll 4
    for (int p4 = 0; p4 < NPOS / 4; p4++) {
        unsigned c4 = mrow[p4];
        #pragma unroll
        for (int i = 0; i < 4; i++) {
            int c = (c4 >> (8 * i)) & 255;
            int p = p4 * 4 + i;
            uint4 u = __ldg(Wb + (((p << 8) + c) << 4));
            add2(acc[0], h2f2(u.x));
            add2(acc[1], h2f2(u.y));
            add2(acc[2], h2f2(u.z));
            add2(acc[3], h2f2(u.w));
        }
    }

    int row = row0 + rowL;
    if (row < B) {
        float4 v0, v1; float lo, hi;
        upk2(acc[0], lo, hi); v0.x = elu1(lo); v0.y = elu1(hi);
        upk2(acc[1], lo, hi); v0.z = elu1(lo); v0.w = elu1(hi);
        upk2(acc[2], lo, hi); v1.x = elu1(lo); v1.y = elu1(hi);
        upk2(acc[3], lo, hi); v1.z = elu1(lo); v1.w = elu1(hi);
        ((float4*)g_h0)[row * 32 + colg * 2]     = v0;
        ((float4*)g_h0)[row * 32 + colg * 2 + 1] = v1;
    }
}

// ============================================================================
// Phase 2: 3 dense layers, f32x2 over k-parity, pre-paired weights: staging
// is a straight 64KB vectorized copy from g_Wp.
// ============================================================================
#define MTILE 28
#define MTHREADS 224
#define MSMEM_FLOATS (16384 + MTILE * HID * 2)
#define MSMEM_BYTES  (MSMEM_FLOATS * 4)

__global__ __launch_bounds__(MTHREADS, 2)
void mlp_kernel(const float* __restrict__ b2,
                const float* __restrict__ b3,
                const float* __restrict__ b4,
                float* __restrict__ out, int B)
{
    extern __shared__ float smem[];
    float4*     plane4 = (float4*)smem;
    ulonglong2* planeU = (ulonglong2*)smem;
    float4*     hA4    = (float4*)(smem + 16384);
    float4*     hB4    = (float4*)(smem + 16384 + MTILE * HID);

    const int t    = threadIdx.x;
    const int row0 = blockIdx.x * MTILE;

    for (int idx = t; idx < MTILE * 32; idx += MTHREADS) {
        hA4[idx] = ((const float4*)g_h0)[row0 * 32 + idx];
    }

    const int j4 = t & 31;
    const int r0 = (t >> 5) * 4;

    const float* bg[3] = {b2, b3, b4};

    #pragma unroll 1
    for (int layer = 0; layer < 3; layer++) {
        const float4* hin  = (layer == 1) ? hB4 : hA4;
        float4*       hout = (layer == 1) ? hA4 : hB4;
        const bool    last = (layer == 2);

        // Straight copy of pre-paired weights (64 KB from L2).
        const float4* Wg4 = (const float4*)g_Wp + layer * 4096;
        #pragma unroll 4
        for (int i = t; i < 4096; i += MTHREADS) plane4[i] = __ldg(&Wg4[i]);
        __syncthreads();

        unsigned long long a[4][4];
        {
            float4 bias = __ldg(&((const float4*)bg[layer])[j4]);
            #pragma unroll
            for (int r = 0; r < 4; r++) {
                a[r][0] = pk2(bias.x, 0.0f);
                a[r][1] = pk2(bias.y, 0.0f);
                a[r][2] = pk2(bias.z, 0.0f);
                a[r][3] = pk2(bias.w, 0.0f);
            }
        }

        #pragma unroll 4
        for (int k4 = 0; k4 < 32; k4++) {
            int k2 = 2 * k4;
            ulonglong2 wA0 = planeU[k2 * 32 + j4];
            ulonglong2 wB0 = planeU[2048 + k2 * 32 + j4];
            ulonglong2 wA1 = planeU[(k2 + 1) * 32 + j4];
            ulonglong2 wB1 = planeU[2048 + (k2 + 1) * 32 + j4];
            #pragma unroll
            for (int r = 0; r < 4; r++) {
                ulonglong2 hv = *(const ulonglong2*)&hin[(r0 + r) * 32 + k4];
                fma2(a[r][0], hv.x, wA0.x);
                fma2(a[r][1], hv.x, wA0.y);
                fma2(a[r][2], hv.x, wB0.x);
                fma2(a[r][3], hv.x, wB0.y);
                fma2(a[r][0], hv.y, wA1.x);
                fma2(a[r][1], hv.y, wA1.y);
                fma2(a[r][2], hv.y, wB1.x);
                fma2(a[r][3], hv.y, wB1.y);
            }
        }

        if (!last) {
            #pragma unroll
            for (int r = 0; r < 4; r++) {
                float4 v; float lo, hi;
                upk2(a[r][0], lo, hi); v.x = elu1(lo + hi);
                upk2(a[r][1], lo, hi); v.y = elu1(lo + hi);
                upk2(a[r][2], lo, hi); v.z = elu1(lo + hi);
                upk2(a[r][3], lo, hi); v.w = elu1(lo + hi);
                hout[(r0 + r) * 32 + j4] = v;
            }
            __syncthreads();
        } else {
            #pragma unroll
            for (int r = 0; r < 4; r++) {
                int row = row0 + r0 + r;
                if (row < B) {
                    float4 v; float lo, hi;
                    upk2(a[r][0], lo, hi); v.x = elu1(lo + hi);
                    upk2(a[r][1], lo, hi); v.y = elu1(lo + hi);
                    upk2(a[r][2], lo, hi); v.z = elu1(lo + hi);
                    upk2(a[r][3], lo, hi); v.w = elu1(lo + hi);
                    ((float4*)out)[row * 32 + j4] = v;
                }
            }
        }
    }
}

extern "C" void kernel_launch(void* const* d_in, const int* in_sizes, int n_in,
                              void* d_out, int out_size)
{
    const int*   msg = (const int*)  d_in[0];
    const float* W1  = (const float*)d_in[1];
    const float* b1  = (const float*)d_in[2];
    const float* W2  = (const float*)d_in[3];
    const float* b2  = (const float*)d_in[4];
    const float* W3  = (const float*)d_in[5];
    const float* b3  = (const float*)d_in[6];
    const float* W4  = (const float*)d_in[7];
    const float* b4  = (const float*)d_in[8];
    float* out = (float*)d_out;

    const int B = in_sizes[0] / NPOS;   // 8192

    cudaFuncSetAttribute(mlp_kernel,
                         cudaFuncAttributeMaxDynamicSharedMemorySize, MSMEM_BYTES);

    convert_kernel<<<CBLOCKS, CTHREADS>>>(W1, W2, W3, W4, msg);

    int ggrid = (B + GTILE - 1) / GTILE;   // 512
    gather_kernel<<<ggrid, GTHREADS>>>(msg, b1, B);

    int mgrid = (B + MTILE - 1) / MTILE;   // 293
    mlp_kernel<<<mgrid, MTHREADS, MSMEM_BYTES>>>(b2, b3, b4, out, B);
}

// round 9
// speedup vs baseline: 1.8375x; 1.0429x over previous
#include <cuda_runtime.h>
#include <cuda_fp16.h>
#include <math.h>
#include <stdint.h>

#define NPOS    80
#define HID     128
#define MAXB    8192

// ---- device scratch ----
__device__ __half g_W1h[NPOS * 256 * HID];    // 5.25 MB fp16 copy of W1
__device__ float  g_Wp[3 * 4096 * 4];         // pre-paired W2/W3/W4 (192 KB)
__device__ float  g_h0[(MAXB + 64) * HID];    // post-ELU h0
__device__ int    g_msg_is64;

__device__ __forceinline__ float elu1(float x) {
    return x > 0.0f ? x : expm1f(x);
}

// ---- f32x2 packed helpers ----
__device__ __forceinline__ unsigned long long pk2(float lo, float hi) {
    unsigned long long r;
    asm("mov.b64 %0, {%1, %2};" : "=l"(r) : "f"(lo), "f"(hi));
    return r;
}
__device__ __forceinline__ void upk2(unsigned long long v, float& lo, float& hi) {
    asm("mov.b64 {%0, %1}, %2;" : "=f"(lo), "=f"(hi) : "l"(v));
}
__device__ __forceinline__ void fma2(unsigned long long& d,
                                     unsigned long long a, unsigned long long b) {
    asm("fma.rn.f32x2 %0, %1, %2, %0;" : "+l"(d) : "l"(a), "l"(b));
}
__device__ __forceinline__ void add2(unsigned long long& d, unsigned long long a) {
    asm("add.rn.f32x2 %0, %0, %1;" : "+l"(d) : "l"(a));
}
__device__ __forceinline__ unsigned long long h2f2(unsigned u) {
    float2 f = __half22float2(*(const __half2*)&u);
    return *(unsigned long long*)&f;
}

// ============================================================================
// Phase 0: (a) W1 -> fp16, 8 float4/thread; __launch_bounds__(.,1) so ptxas
// can keep all 8 loads in registers (round-7 had regs=32 -> serialized).
// (b) pre-pair W2/3/4; (c) int64 detect.
// ============================================================================
#define CTHREADS 256
#define CW1BLOCKS 320                 // 320*256*8 = 655360 float4 = full W1
#define CPAIRBLOCKS 24                // 24*256 = 6144 pairing tasks
#define CBLOCKS (CW1BLOCKS + CPAIRBLOCKS)

__global__ __launch_bounds__(CTHREADS, 1)
void convert_kernel(const float* __restrict__ W1,
                    const float* __restrict__ W2,
                    const float* __restrict__ W3,
                    const float* __restrict__ W4,
                    const int* __restrict__ msg)
{
    const int bx = blockIdx.x;
    const int t  = threadIdx.x;

    if (bx == 0 && t < 32) {
        int v = 0;
        #pragma unroll 4
        for (int i = t; i < 2048; i += 32) v |= __ldg(&msg[2 * i + 1]);
        unsigned ball = __ballot_sync(0xFFFFFFFFu, v != 0);
        if (t == 0) g_msg_is64 = (ball == 0u) ? 1 : 0;
    }

    if (bx < CW1BLOCKS) {
        const int base = bx * CTHREADS + t;
        const int step = CW1BLOCKS * CTHREADS;
        float4 v0 = __ldg(&((const float4*)W1)[base + 0 * step]);
        float4 v1 = __ldg(&((const float4*)W1)[base + 1 * step]);
        float4 v2 = __ldg(&((const float4*)W1)[base + 2 * step]);
        float4 v3 = __ldg(&((const float4*)W1)[base + 3 * step]);
        float4 v4 = __ldg(&((const float4*)W1)[base + 4 * step]);
        float4 v5 = __ldg(&((const float4*)W1)[base + 5 * step]);
        float4 v6 = __ldg(&((const float4*)W1)[base + 6 * step]);
        float4 v7 = __ldg(&((const float4*)W1)[base + 7 * step]);
        float4 vv[8] = {v0, v1, v2, v3, v4, v5, v6, v7};
        #pragma unroll
        for (int j = 0; j < 8; j++) {
            __half2 h0 = __floats2half2_rn(vv[j].x, vv[j].y);
            __half2 h1 = __floats2half2_rn(vv[j].z, vv[j].w);
            uint2 o;
            o.x = *(unsigned*)&h0;
            o.y = *(unsigned*)&h1;
            ((uint2*)g_W1h)[base + j * step] = o;
        }
    } else {
        int task  = (bx - CW1BLOCKS) * CTHREADS + t;   // 0..6143
        int layer = task >> 11;
        int i     = task & 2047;
        int k2 = i >> 5;
        int j  = i & 31;
        const float* Wsrc = (layer == 0) ? W2 : (layer == 1) ? W3 : W4;
        float4 a = __ldg(&((const float4*)Wsrc)[(2 * k2) * 32 + j]);
        float4 b = __ldg(&((const float4*)Wsrc)[(2 * k2 + 1) * 32 + j]);
        float4 pA; pA.x = a.x; pA.y = b.x; pA.z = a.y; pA.w = b.y;
        float4 pB; pB.x = a.z; pB.y = b.z; pB.z = a.w; pB.w = b.w;
        ((float4*)g_Wp)[layer * 4096 + i]        = pA;
        ((float4*)g_Wp)[layer * 4096 + 2048 + i] = pB;
    }
}

// ============================================================================
// Phase 1: gather (fp16 table, f32x2 accumulate). 512 CTAs x 8 warps.
// Lanes 0-15 serve row A, 16-31 row B; lane owns 16B (8 hid cols) of the
// 256B fp16 table row -> one LDG.128 per (2 rows, position).
// ============================================================================
#define GTILE 16
#define GTHREADS 256

__global__ __launch_bounds__(GTHREADS)
void gather_kernel(const int* __restrict__ msg,
                   const float* __restrict__ b1, int B)
{
    __shared__ unsigned char msg_sh[GTILE * NPOS];   // [r][p]

    const int t    = threadIdx.x;
    const int row0 = blockIdx.x * GTILE;
    const int is64 = g_msg_is64;

    for (int idx = t; idx < GTILE * NPOS; idx += GTHREADS) {
        int r = idx / NPOS;
        int p = idx - r * NPOS;
        int row = row0 + r;
        int c = 0;
        if (row < B) {
            int gi = row * NPOS + p;
            c = is64 ? __ldg(&msg[2 * gi]) : __ldg(&msg[gi]);
        }
        msg_sh[idx] = (unsigned char)c;
    }
    __syncthreads();

    const int lane = t & 31;
    const int w    = t >> 5;
    const int hsel = lane >> 4;
    const int colg = lane & 15;
    const int rowL = w * 2 + hsel;

    unsigned long long acc[4];
    {
        float4 b0 = __ldg(&((const float4*)b1)[colg * 2]);
        float4 b1v = __ldg(&((const float4*)b1)[colg * 2 + 1]);
        acc[0] = pk2(b0.x, b0.y);
        acc[1] = pk2(b0.z, b0.w);
        acc[2] = pk2(b1v.x, b1v.y);
        acc[3] = pk2(b1v.z, b1v.w);
    }

    const uint4* Wb = (const uint4*)g_W1h + colg;
    const unsigned* mrow = (const unsigned*)(msg_sh + rowL * NPOS);

    #pragma unroll 4
    for (int p4 = 0; p4 < NPOS / 4; p4++) {
        unsigned c4 = mrow[p4];
        #pragma unroll
        for (int i = 0; i < 4; i++) {
            int c = (c4 >> (8 * i)) & 255;
            int p = p4 * 4 + i;
            uint4 u = __ldg(Wb + (((p << 8) + c) << 4));
            add2(acc[0], h2f2(u.x));
            add2(acc[1], h2f2(u.y));
            add2(acc[2], h2f2(u.z));
            add2(acc[3], h2f2(u.w));
        }
    }

    int row = row0 + rowL;
    if (row < B) {
        float4 v0, v1; float lo, hi;
        upk2(acc[0], lo, hi); v0.x = elu1(lo); v0.y = elu1(hi);
        upk2(acc[1], lo, hi); v0.z = elu1(lo); v0.w = elu1(hi);
        upk2(acc[2], lo, hi); v1.x = elu1(lo); v1.y = elu1(hi);
        upk2(acc[3], lo, hi); v1.z = elu1(lo); v1.w = elu1(hi);
        ((float4*)g_h0)[row * 32 + colg * 2]     = v0;
        ((float4*)g_h0)[row * 32 + colg * 2 + 1] = v1;
    }
}

// ============================================================================
// Phase 2: 3 dense layers. MTILE 56, 448 threads, occ 1 -> weight staging
// traffic halved (28 MB chip-wide) and one wave (147 CTAs on 148 SMs).
// 4x4 thread tile (14 warps x 4 rows), f32x2 over k-parity.
// ============================================================================
#define MTILE 56
#define MTHREADS 448
#define MSMEM_FLOATS (16384 + MTILE * HID * 2)   // 64KB planes + 28KB hA + 28KB hB
#define MSMEM_BYTES  (MSMEM_FLOATS * 4)

__global__ __launch_bounds__(MTHREADS, 1)
void mlp_kernel(const float* __restrict__ b2,
                const float* __restrict__ b3,
                const float* __restrict__ b4,
                float* __restrict__ out, int B)
{
    extern __shared__ float smem[];
    float4*     plane4 = (float4*)smem;
    ulonglong2* planeU = (ulonglong2*)smem;
    float4*     hA4    = (float4*)(smem + 16384);
    float4*     hB4    = (float4*)(smem + 16384 + MTILE * HID);

    const int t    = threadIdx.x;
    const int row0 = blockIdx.x * MTILE;

    for (int idx = t; idx < MTILE * 32; idx += MTHREADS) {
        hA4[idx] = ((const float4*)g_h0)[row0 * 32 + idx];
    }

    const int j4 = t & 31;
    const int r0 = (t >> 5) * 4;    // 14 warps x 4 rows = 56

    const float* bg[3] = {b2, b3, b4};

    #pragma unroll 1
    for (int layer = 0; layer < 3; layer++) {
        const float4* hin  = (layer == 1) ? hB4 : hA4;
        float4*       hout = (layer == 1) ? hA4 : hB4;
        const bool    last = (layer == 2);

        const float4* Wg4 = (const float4*)g_Wp + layer * 4096;
        for (int i = t; i < 4096; i += MTHREADS) plane4[i] = __ldg(&Wg4[i]);
        __syncthreads();

        unsigned long long a[4][4];
        {
            float4 bias = __ldg(&((const float4*)bg[layer])[j4]);
            #pragma unroll
            for (int r = 0; r < 4; r++) {
                a[r][0] = pk2(bias.x, 0.0f);
                a[r][1] = pk2(bias.y, 0.0f);
                a[r][2] = pk2(bias.z, 0.0f);
                a[r][3] = pk2(bias.w, 0.0f);
            }
        }

        #pragma unroll 4
        for (int k4 = 0; k4 < 32; k4++) {
            int k2 = 2 * k4;
            ulonglong2 wA0 = planeU[k2 * 32 + j4];
            ulonglong2 wB0 = planeU[2048 + k2 * 32 + j4];
            ulonglong2 wA1 = planeU[(k2 + 1) * 32 + j4];
            ulonglong2 wB1 = planeU[2048 + (k2 + 1) * 32 + j4];
            #pragma unroll
            for (int r = 0; r < 4; r++) {
                ulonglong2 hv = *(const ulonglong2*)&hin[(r0 + r) * 32 + k4];
                fma2(a[r][0], hv.x, wA0.x);
                fma2(a[r][1], hv.x, wA0.y);
                fma2(a[r][2], hv.x, wB0.x);
                fma2(a[r][3], hv.x, wB0.y);
                fma2(a[r][0], hv.y, wA1.x);
                fma2(a[r][1], hv.y, wA1.y);
                fma2(a[r][2], hv.y, wB1.x);
                fma2(a[r][3], hv.y, wB1.y);
            }
        }

        if (!last) {
            #pragma unroll
            for (int r = 0; r < 4; r++) {
                float4 v; float lo, hi;
                upk2(a[r][0], lo, hi); v.x = elu1(lo + hi);
                upk2(a[r][1], lo, hi); v.y = elu1(lo + hi);
                upk2(a[r][2], lo, hi); v.z = elu1(lo + hi);
                upk2(a[r][3], lo, hi); v.w = elu1(lo + hi);
                hout[(r0 + r) * 32 + j4] = v;
            }
            __syncthreads();
        } else {
            #pragma unroll
            for (int r = 0; r < 4; r++) {
                int row = row0 + r0 + r;
                if (row < B) {
                    float4 v; float lo, hi;
                    upk2(a[r][0], lo, hi); v.x = elu1(lo + hi);
                    upk2(a[r][1], lo, hi); v.y = elu1(lo + hi);
                    upk2(a[r][2], lo, hi); v.z = elu1(lo + hi);
                    upk2(a[r][3], lo, hi); v.w = elu1(lo + hi);
                    ((float4*)out)[row * 32 + j4] = v;
                }
            }
        }
    }
}

extern "C" void kernel_launch(void* const* d_in, const int* in_sizes, int n_in,
                              void* d_out, int out_size)
{
    const int*   msg = (const int*)  d_in[0];
    const float* W1  = (const float*)d_in[1];
    const float* b1  = (const float*)d_in[2];
    const float* W2  = (const float*)d_in[3];
    const float* b2  = (const float*)d_in[4];
    const float* W3  = (const float*)d_in[5];
    const float* b3  = (const float*)d_in[6];
    const float* W4  = (const float*)d_in[7];
    const float* b4  = (const float*)d_in[8];
    float* out = (float*)d_out;

    const int B = in_sizes[0] / NPOS;   // 8192

    cudaFuncSetAttribute(mlp_kernel,
                         cudaFuncAttributeMaxDynamicSharedMemorySize, MSMEM_BYTES);

    convert_kernel<<<CBLOCKS, CTHREADS>>>(W1, W2, W3, W4, msg);

    int ggrid = (B + GTILE - 1) / GTILE;   // 512
    gather_kernel<<<ggrid, GTHREADS>>>(msg, b1, B);

    int mgrid = (B + MTILE - 1) / MTILE;   // 147
    mlp_kernel<<<mgrid, MTHREADS, MSMEM_BYTES>>>(b2, b3, b4, out, B);
}